// round 16
// baseline (speedup 1.0000x reference)
#include <cuda_runtime.h>

#define IN_F   4096
#define OUT_F  11008
#define NC     16
#define TOPK   1024

__device__ float g_masks[NC * IN_F];   // per-center masked-x candidates
__device__ float g_d2[NC];             // per-center score (same argmin as d2)

// ---------------------------------------------------------------------------
// Kernel 1: 16 blocks x 1024 threads, fully independent (no inter-block sync).
// PDL trigger at entry -> matvec grid launches immediately and prefetches W.
// Block c: ONE fused reduction (s=sum e, ce=c.e, cc=||c||^2) ->
// score_c = cc - 2*ce/s  (== d2_c - ||a||^2, same argmin),
// then exact top-1024 select of center c via 3-pass radix -> g_masks[c].
// ---------------------------------------------------------------------------
__global__ void __launch_bounds__(1024)
prep_kernel(const float* __restrict__ x,
            const float* __restrict__ centers)
{
    cudaTriggerProgrammaticLaunchCompletion();

    __shared__ float    s_red[96];        // 3 x 32 warp partials
    __shared__ float    s_b[3];
    __shared__ unsigned s_hist[3][2048];  // 3 radix passes, 11-bit digits
    __shared__ unsigned s_wsum[32];
    __shared__ int      s_ints[2];        // [0]=remaining [1]=prefix
    __shared__ int      s_warp[32];

    const int tid  = threadIdx.x;
    const int lane = tid & 31;
    const int wid  = tid >> 5;
    const int c    = blockIdx.x;

    // clear all 3 histograms: 6144 entries, 6 per thread
#pragma unroll
    for (int k = 0; k < 6; k++)
        ((unsigned*)s_hist)[tid + 1024 * k] = 0u;

    // ---- loads (independent, issued together) ----
    const float4 xv = reinterpret_cast<const float4*>(x)[tid];
    const float4 cv = reinterpret_cast<const float4*>(centers)[c * (IN_F / 4) + tid];

    // ---- fused: e=exp|x| (no max-sub; feeds only argmin), s, c.e, ||c||^2 ----
    float e[4] = { expf(fabsf(xv.x)), expf(fabsf(xv.y)),
                   expf(fabsf(xv.z)), expf(fabsf(xv.w)) };
    float s  = e[0] + e[1] + e[2] + e[3];
    float ce = cv.x * e[0] + cv.y * e[1] + cv.z * e[2] + cv.w * e[3];
    float cc = cv.x * cv.x + cv.y * cv.y + cv.z * cv.z + cv.w * cv.w;
#pragma unroll
    for (int o = 16; o > 0; o >>= 1) {
        s  += __shfl_xor_sync(0xffffffffu, s,  o);
        ce += __shfl_xor_sync(0xffffffffu, ce, o);
        cc += __shfl_xor_sync(0xffffffffu, cc, o);
    }
    if (lane == 0) { s_red[wid] = s; s_red[32 + wid] = ce; s_red[64 + wid] = cc; }
    __syncthreads();
    if (wid == 0) {
        float r0 = s_red[lane], r1 = s_red[32 + lane], r2 = s_red[64 + lane];
#pragma unroll
        for (int o = 16; o > 0; o >>= 1) {
            r0 += __shfl_xor_sync(0xffffffffu, r0, o);
            r1 += __shfl_xor_sync(0xffffffffu, r1, o);
            r2 += __shfl_xor_sync(0xffffffffu, r2, o);
        }
        if (lane == 0) {
            g_d2[c] = r2 - 2.f * r1 / r0;   // score: same argmin as d2
        }
    }

    // ---- local exact top-1024 select of center c (keys in registers) ----
    const unsigned key[4] = { __float_as_uint(cv.x), __float_as_uint(cv.y),
                              __float_as_uint(cv.z), __float_as_uint(cv.w) };

    // 3-pass radix: digit shifts 21 / 10 / 0 (11,11,10 bits; 2048-bin scans,
    // last pass only populates bins 0..1023 -- harmless)
    const int SHIFT[3] = { 21, 10, 0 };

    unsigned prefix    = 0;
    int      remaining = TOPK;
#pragma unroll
    for (int p = 0; p < 3; p++) {
        const int shift = SHIFT[p];
#pragma unroll
        for (int j = 0; j < 4; j++) {
            bool match = (p == 0) ||
                         ((key[j] >> (shift + 11)) == (prefix >> (shift + 11)));
            if (match) atomicAdd(&s_hist[p][(key[j] >> shift) & 0x7FFu], 1u);
        }
        __syncthreads();
        // suffix scan over 2048 bins: thread t owns bins 2t, 2t+1
        const unsigned h0 = s_hist[p][2 * tid];
        const unsigned h1 = s_hist[p][2 * tid + 1];
        unsigned v = h0 + h1;
#pragma unroll
        for (int off = 1; off < 32; off <<= 1) {
            unsigned n = __shfl_down_sync(0xffffffffu, v, off);
            if (lane + off < 32) v += n;
        }
        if (lane == 0) s_wsum[wid] = v;
        __syncthreads();
        unsigned woff = 0;
        for (int w2 = wid + 1; w2 < 32; w2++) woff += s_wsum[w2];
        // re-derive this thread's inclusive suffix within warp
        unsigned vt = h0 + h1;
        {
            // recompute suffix including own: shuffle again (cheap) — use the
            // same pattern as above
#pragma unroll
            for (int off = 1; off < 32; off <<= 1) {
                unsigned n = __shfl_down_sync(0xffffffffu, vt, off);
                if (lane + off < 32) vt += n;
            }
        }
        const unsigned suffix = vt + woff;       // sum of h over bins >= 2t
        // bin 2t:   ge = suffix,        gt = suffix - h0
        // bin 2t+1: ge = suffix - h0,   gt = suffix - h0 - h1
        {
            unsigned ge0 = suffix,      gt0 = suffix - h0;
            unsigned ge1 = suffix - h0, gt1 = suffix - h0 - h1;
            if ((int)ge0 >= remaining && (int)gt0 < remaining) {
                s_ints[0] = remaining - (int)gt0;
                s_ints[1] = (int)(prefix | ((unsigned)(2 * tid) << shift));
            }
            if ((int)ge1 >= remaining && (int)gt1 < remaining) {
                s_ints[0] = remaining - (int)gt1;
                s_ints[1] = (int)(prefix | ((unsigned)(2 * tid + 1) << shift));
            }
        }
        __syncthreads();
        remaining = s_ints[0];
        prefix    = (unsigned)s_ints[1];
        __syncthreads();
    }
    const unsigned T = prefix;
    const int      R = remaining;              // R lowest-index ties (jax order)

    // tie-rank prefix scan (index order)
    int cnt4[4];
    int tot = 0;
#pragma unroll
    for (int j = 0; j < 4; j++) {
        cnt4[j] = tot;
        tot += (key[j] == T) ? 1 : 0;
    }
    int incl = tot;
#pragma unroll
    for (int off = 1; off < 32; off <<= 1) {
        int n = __shfl_up_sync(0xffffffffu, incl, off);
        if (lane >= off) incl += n;
    }
    if (lane == 31) s_warp[wid] = incl;
    __syncthreads();
    if (wid == 0) {
        int v = s_warp[lane];
#pragma unroll
        for (int off = 1; off < 32; off <<= 1) {
            int n = __shfl_up_sync(0xffffffffu, v, off);
            if (lane >= off) v += n;
        }
        s_warp[lane] = v;
    }
    __syncthreads();
    const int excl = incl - tot + (wid > 0 ? s_warp[wid - 1] : 0);
    const float xin[4] = { xv.x, xv.y, xv.z, xv.w };
    float o4[4];
#pragma unroll
    for (int j = 0; j < 4; j++) {
        bool sel = (key[j] > T) || (key[j] == T && (excl + cnt4[j]) < R);
        o4[j] = sel ? xin[j] : 0.f;
    }
    reinterpret_cast<float4*>(g_masks)[c * (IN_F / 4) + tid] =
        make_float4(o4[0], o4[1], o4[2], o4[3]);
}

// ---------------------------------------------------------------------------
// Kernel 2: out = W @ g_masks[argmin score] + bias. R1's best-measured config
// (grid=1376, block=256, 1 row/warp, unroll 8). Deep L2 prefetch (6KB/warp)
// + early bias load + PDL sync, then per-block argmin.
// ---------------------------------------------------------------------------
__global__ void __launch_bounds__(256)
matvec_kernel(const float* __restrict__ W,
              const float* __restrict__ bias,
              float* __restrict__ out)
{
    __shared__ float4 sx[IN_F / 4];
    __shared__ int    s_ci;
    const int tid  = threadIdx.x;
    const int warp = tid >> 5;
    const int lane = tid & 31;
    const int row  = blockIdx.x * 8 + warp;   // 11008 = 1376 * 8, in range

    const float4* wr = reinterpret_cast<const float4*>(W + (size_t)row * IN_F);

    // ---- early bias load (independent of prep) ----
    const float b = bias[row];

    // ---- deep L2 prefetch: first 6KB of this warp's row (runs during prep) ----
#pragma unroll
    for (int k = 0; k < 12; k++) {
        const float4* p = wr + lane + 32 * k;
        float pa, pb, pc, pd;
        asm volatile("ld.global.cg.v4.f32 {%0,%1,%2,%3}, [%4];"
                     : "=f"(pa), "=f"(pb), "=f"(pc), "=f"(pd)
                     : "l"(p));
    }

    // ---- wait for prep grid completion (memory visible); no-op if serial ----
    cudaGridDependencySynchronize();

    if (tid == 0) {
        int best = 0;
        float bv = g_d2[0];
#pragma unroll
        for (int k = 1; k < NC; k++)
            if (g_d2[k] < bv) { bv = g_d2[k]; best = k; }   // first-min tie-break
        s_ci = best;
    }
    __syncthreads();
    const float4* xm = reinterpret_cast<const float4*>(g_masks) + s_ci * (IN_F / 4);
    for (int i = tid; i < IN_F / 4; i += 256)
        sx[i] = xm[i];
    __syncthreads();

    float acc = 0.f;
#pragma unroll 8
    for (int j = lane; j < IN_F / 4; j += 32) {
        float4 w  = wr[j];
        float4 xv = sx[j];
        acc += w.x * xv.x + w.y * xv.y + w.z * xv.z + w.w * xv.w;
    }
#pragma unroll
    for (int o = 16; o > 0; o >>= 1)
        acc += __shfl_xor_sync(0xffffffffu, acc, o);
    if (lane == 0)
        out[row] = acc + b;
}

// ---------------------------------------------------------------------------
extern "C" void kernel_launch(void* const* d_in, const int* in_sizes, int n_in,
                              void* d_out, int out_size)
{
    const float* x       = (const float*)d_in[0];  // [4096]
    const float* weight  = (const float*)d_in[1];  // [11008, 4096]
    const float* bias    = (const float*)d_in[2];  // [11008]
    const float* centers = (const float*)d_in[3];  // [16, 4096]
    float*       out     = (float*)d_out;          // [11008]

    prep_kernel<<<NC, 1024>>>(x, centers);

    // PDL launch: matvec begins (prefetching) while prep runs.
    cudaLaunchConfig_t cfg = {};
    cfg.gridDim  = dim3(OUT_F / 8);
    cfg.blockDim = dim3(256);
    cfg.stream   = 0;
    cudaLaunchAttribute attr[1];
    attr[0].id = cudaLaunchAttributeProgrammaticStreamSerialization;
    attr[0].val.programmaticStreamSerializationAllowed = 1;
    cfg.attrs    = attr;
    cfg.numAttrs = 1;
    cudaLaunchKernelEx(&cfg, matvec_kernel, weight, bias, out);
}

// round 17
// speedup vs baseline: 1.0339x; 1.0339x over previous
#include <cuda_runtime.h>

#define IN_F   4096
#define OUT_F  11008
#define NC     16
#define TOPK   1024

__device__ float g_masks[NC * IN_F];   // per-center masked-x candidates
__device__ float g_d2[NC];             // per-center score (same argmin as d2)

// ---------------------------------------------------------------------------
// Kernel 1: 16 blocks x 1024 threads, fully independent (no inter-block sync).
// PDL trigger at entry -> matvec grid launches immediately and prefetches W.
// Block c: ONE fused reduction (s=sum e, ce=c.e, cc=||c||^2) ->
// score_c = cc - 2*ce/s (same argmin as d2), then exact top-1024 select of
// center c (R15's proven 4-pass radix) -> g_masks[c].
// ---------------------------------------------------------------------------
__global__ void __launch_bounds__(1024)
prep_kernel(const float* __restrict__ x,
            const float* __restrict__ centers)
{
    cudaTriggerProgrammaticLaunchCompletion();

    __shared__ float    s_red[96];     // 3 x 32 warp partials
    __shared__ unsigned s_hist[4][256];
    __shared__ unsigned s_wsum[8];
    __shared__ int      s_ints[2];     // [0]=remaining [1]=prefix
    __shared__ int      s_warp[32];

    const int tid  = threadIdx.x;
    const int lane = tid & 31;
    const int wid  = tid >> 5;
    const int c    = blockIdx.x;

    ((unsigned*)s_hist)[tid] = 0u;     // clear all 4 histograms (1 entry/thread)

    // ---- loads (independent, issued together) ----
    const float4 xv = reinterpret_cast<const float4*>(x)[tid];
    const float4 cv = reinterpret_cast<const float4*>(centers)[c * (IN_F / 4) + tid];

    // ---- fused: e=exp|x| (no max-sub; feeds only argmin), s, c.e, ||c||^2 ----
    float e[4] = { expf(fabsf(xv.x)), expf(fabsf(xv.y)),
                   expf(fabsf(xv.z)), expf(fabsf(xv.w)) };
    float s  = e[0] + e[1] + e[2] + e[3];
    float ce = cv.x * e[0] + cv.y * e[1] + cv.z * e[2] + cv.w * e[3];
    float cc = cv.x * cv.x + cv.y * cv.y + cv.z * cv.z + cv.w * cv.w;
#pragma unroll
    for (int o = 16; o > 0; o >>= 1) {
        s  += __shfl_xor_sync(0xffffffffu, s,  o);
        ce += __shfl_xor_sync(0xffffffffu, ce, o);
        cc += __shfl_xor_sync(0xffffffffu, cc, o);
    }
    if (lane == 0) { s_red[wid] = s; s_red[32 + wid] = ce; s_red[64 + wid] = cc; }
    __syncthreads();
    if (wid == 0) {
        float r0 = s_red[lane], r1 = s_red[32 + lane], r2 = s_red[64 + lane];
#pragma unroll
        for (int o = 16; o > 0; o >>= 1) {
            r0 += __shfl_xor_sync(0xffffffffu, r0, o);
            r1 += __shfl_xor_sync(0xffffffffu, r1, o);
            r2 += __shfl_xor_sync(0xffffffffu, r2, o);
        }
        if (lane == 0)
            g_d2[c] = r2 - 2.f * r1 / r0;   // score: same argmin as d2
    }

    // ---- local exact top-1024 select of center c (keys in registers) ----
    const unsigned key[4] = { __float_as_uint(cv.x), __float_as_uint(cv.y),
                              __float_as_uint(cv.z), __float_as_uint(cv.w) };

    unsigned prefix    = 0;
    int      remaining = TOPK;
#pragma unroll
    for (int p = 0; p < 4; p++) {
        const int shift = 24 - 8 * p;
#pragma unroll
        for (int j = 0; j < 4; j++) {
            bool match = (p == 0) ||
                         ((key[j] >> (shift + 8)) == (prefix >> (shift + 8)));
            if (match) atomicAdd(&s_hist[p][(key[j] >> shift) & 255u], 1u);
        }
        __syncthreads();
        unsigned v = 0, cnt = 0;
        if (tid < 256) {
            cnt = s_hist[p][tid];
            v = cnt;
#pragma unroll
            for (int off = 1; off < 32; off <<= 1) {
                unsigned n = __shfl_down_sync(0xffffffffu, v, off);
                if (lane + off < 32) v += n;
            }
            if (lane == 0) s_wsum[wid] = v;
        }
        __syncthreads();
        if (tid < 256) {
            unsigned off = 0;
            for (int w2 = wid + 1; w2 < 8; w2++) off += s_wsum[w2];
            unsigned ge = v + off;             // #keys byte >= tid (among matching)
            unsigned gt = ge - cnt;            // #keys byte >  tid
            if ((int)ge >= remaining && (int)gt < remaining) {   // unique crossing
                s_ints[0] = remaining - (int)gt;
                s_ints[1] = (int)(prefix | ((unsigned)tid << shift));
            }
        }
        __syncthreads();
        remaining = s_ints[0];
        prefix    = (unsigned)s_ints[1];
        __syncthreads();
    }
    const unsigned T = prefix;
    const int      R = remaining;              // R lowest-index ties (jax order)

    // tie-rank prefix scan (index order)
    int cnt4[4];
    int tot = 0;
#pragma unroll
    for (int j = 0; j < 4; j++) {
        cnt4[j] = tot;
        tot += (key[j] == T) ? 1 : 0;
    }
    int incl = tot;
#pragma unroll
    for (int off = 1; off < 32; off <<= 1) {
        int n = __shfl_up_sync(0xffffffffu, incl, off);
        if (lane >= off) incl += n;
    }
    if (lane == 31) s_warp[wid] = incl;
    __syncthreads();
    if (wid == 0) {
        int v = s_warp[lane];
#pragma unroll
        for (int off = 1; off < 32; off <<= 1) {
            int n = __shfl_up_sync(0xffffffffu, v, off);
            if (lane >= off) v += n;
        }
        s_warp[lane] = v;
    }
    __syncthreads();
    const int excl = incl - tot + (wid > 0 ? s_warp[wid - 1] : 0);
    const float xin[4] = { xv.x, xv.y, xv.z, xv.w };
    float o4[4];
#pragma unroll
    for (int j = 0; j < 4; j++) {
        bool sel = (key[j] > T) || (key[j] == T && (excl + cnt4[j]) < R);
        o4[j] = sel ? xin[j] : 0.f;
    }
    reinterpret_cast<float4*>(g_masks)[c * (IN_F / 4) + tid] =
        make_float4(o4[0], o4[1], o4[2], o4[3]);
}

// ---------------------------------------------------------------------------
// Kernel 2: out = W @ g_masks[argmin score] + bias. R1's best-measured config
// (grid=1376, block=256, 1 row/warp, unroll 8). Deep L2 prefetch (8KB/warp)
// + early bias load + PDL sync, then warp-parallel argmin.
// ---------------------------------------------------------------------------
__global__ void __launch_bounds__(256)
matvec_kernel(const float* __restrict__ W,
              const float* __restrict__ bias,
              float* __restrict__ out)
{
    __shared__ float4 sx[IN_F / 4];
    __shared__ int    s_ci;
    const int tid  = threadIdx.x;
    const int warp = tid >> 5;
    const int lane = tid & 31;
    const int row  = blockIdx.x * 8 + warp;   // 11008 = 1376 * 8, in range

    const float4* wr = reinterpret_cast<const float4*>(W + (size_t)row * IN_F);

    // ---- early bias load (independent of prep) ----
    const float b = bias[row];

    // ---- deep L2 prefetch: first 8KB of this warp's row (runs during prep).
    //      Fire-and-forget: dead destinations, does not delay the sync. ----
#pragma unroll
    for (int k = 0; k < 16; k++) {
        const float4* p = wr + lane + 32 * k;
        float pa, pb, pc, pd;
        asm volatile("ld.global.cg.v4.f32 {%0,%1,%2,%3}, [%4];"
                     : "=f"(pa), "=f"(pb), "=f"(pc), "=f"(pd)
                     : "l"(p));
    }

    // ---- wait for prep grid completion (memory visible); no-op if serial ----
    cudaGridDependencySynchronize();

    // ---- warp-parallel argmin (first-min tie-break == jnp.argmin) ----
    if (tid < 32) {
        float v  = (tid < NC) ? g_d2[tid] : 3.4e38f;
        int   ix = tid;
#pragma unroll
        for (int o = 16; o > 0; o >>= 1) {
            float ov = __shfl_xor_sync(0xffffffffu, v,  o);
            int   oi = __shfl_xor_sync(0xffffffffu, ix, o);
            if (ov < v || (ov == v && oi < ix)) { v = ov; ix = oi; }
        }
        if (tid == 0) s_ci = ix;
    }
    __syncthreads();
    const float4* xm = reinterpret_cast<const float4*>(g_masks) + s_ci * (IN_F / 4);
    for (int i = tid; i < IN_F / 4; i += 256)
        sx[i] = xm[i];
    __syncthreads();

    float acc = 0.f;
#pragma unroll 8
    for (int j = lane; j < IN_F / 4; j += 32) {
        float4 w  = wr[j];
        float4 xv = sx[j];
        acc += w.x * xv.x + w.y * xv.y + w.z * xv.z + w.w * xv.w;
    }
#pragma unroll
    for (int o = 16; o > 0; o >>= 1)
        acc += __shfl_xor_sync(0xffffffffu, acc, o);
    if (lane == 0)
        out[row] = acc + b;
}

// ---------------------------------------------------------------------------
extern "C" void kernel_launch(void* const* d_in, const int* in_sizes, int n_in,
                              void* d_out, int out_size)
{
    const float* x       = (const float*)d_in[0];  // [4096]
    const float* weight  = (const float*)d_in[1];  // [11008, 4096]
    const float* bias    = (const float*)d_in[2];  // [11008]
    const float* centers = (const float*)d_in[3];  // [16, 4096]
    float*       out     = (float*)d_out;          // [11008]

    prep_kernel<<<NC, 1024>>>(x, centers);

    // PDL launch: matvec begins (prefetching) while prep runs.
    cudaLaunchConfig_t cfg = {};
    cfg.gridDim  = dim3(OUT_F / 8);
    cfg.blockDim = dim3(256);
    cfg.stream   = 0;
    cudaLaunchAttribute attr[1];
    attr[0].id = cudaLaunchAttributeProgrammaticStreamSerialization;
    attr[0].val.programmaticStreamSerializationAllowed = 1;
    cfg.attrs    = attr;
    cfg.numAttrs = 1;
    cudaLaunchKernelEx(&cfg, matvec_kernel, weight, bias, out);
}